// round 6
// baseline (speedup 1.0000x reference)
#include <cuda_runtime.h>
#include <cuda_bf16.h>

#define NN   50000
#define EE   800000
#define NEG  0.2f

// ---------------- scratch (static device arrays; no allocation allowed) ----
__device__ float g_xl1 [NN*128];
__device__ float g_xr1 [NN*128];
__device__ float g_h1  [NN*128];
__device__ float g_xl2 [NN*128];
__device__ float g_xr2 [NN*128];
__device__ float g_xres[NN*16];
__device__ int   g_deg [NN];
__device__ int   g_rowptr[NN+1];
__device__ int   g_cursor[NN];
__device__ int   g_csr [EE];

// ---------------- CSR build ------------------------------------------------
__global__ void k_zero_deg() {
    int i = blockIdx.x*256 + threadIdx.x;
    if (i < NN) g_deg[i] = 0;
}

// edge_index is int32 (JAX x64 disabled): row 0 = src [0..E), row 1 = dst [E..2E)
__global__ void k_count(const int* __restrict__ ei) {
    int e = blockIdx.x*256 + threadIdx.x;
    if (e < EE) {
        unsigned dst = (unsigned)ei[EE + e];
        if (dst < NN) atomicAdd(&g_deg[dst], 1);
    }
}

__global__ void __launch_bounds__(1024) k_scan() {
    __shared__ int s[1024];
    const int tid = threadIdx.x;
    const int per = (NN + 1023) / 1024;          // 49
    int start = tid * per;
    int stop  = min(start + per, NN);
    int sum = 0;
    for (int i = start; i < stop; i++) sum += g_deg[i];
    s[tid] = sum;
    __syncthreads();
    for (int off = 1; off < 1024; off <<= 1) {
        int v = (tid >= off) ? s[tid - off] : 0;
        __syncthreads();
        s[tid] += v;
        __syncthreads();
    }
    int run = s[tid] - sum;                      // exclusive offset for this chunk
    for (int i = start; i < stop; i++) {
        g_rowptr[i] = run;
        g_cursor[i] = run;
        run += g_deg[i];
    }
    // total kept edges = last thread's post-loop running value (== inclusive total)
    if (tid == 1023) g_rowptr[NN] = run;
}

__global__ void k_scatter(const int* __restrict__ ei) {
    int e = blockIdx.x*256 + threadIdx.x;
    if (e < EE) {
        unsigned src = (unsigned)ei[e];
        unsigned dst = (unsigned)ei[EE + e];
        if (dst < NN && src < NN) {
            int pos = atomicAdd(&g_cursor[dst], 1);
            g_csr[pos] = (int)src;
        }
    }
}

// ---------------- fused SIMT GEMM (exact fp32) ------------------------------
// out[n][o] = sum_k A[n][k] * Wcat[o][k] + bias[o]
template<bool SKIP>
__global__ void __launch_bounds__(256) k_gemm(
    const float* __restrict__ A,
    const float* __restrict__ W0, const float* __restrict__ B0,
    const float* __restrict__ W1, const float* __restrict__ B1,
    const float* __restrict__ W2,
    float* __restrict__ O0, float* __restrict__ O1, float* __restrict__ O2)
{
    const int OUTS = SKIP ? 272 : 256;
    extern __shared__ float sm[];
    float* sW = sm;                 // OUTS*128
    float* sB = sW + OUTS*128;      // 288 (padded)
    float* sX = sB + 288;           // 64*129

    const int tid = threadIdx.x;

    // weights -> smem (contiguous, float4)
    float4* sw4 = (float4*)sW;
    const float4* w0 = (const float4*)W0;
    for (int i = tid; i < 4096; i += 256) sw4[i] = w0[i];
    const float4* w1 = (const float4*)W1;
    for (int i = tid; i < 4096; i += 256) sw4[4096 + i] = w1[i];
    if (SKIP) {
        const float4* w2 = (const float4*)W2;
        for (int i = tid; i < 512; i += 256) sw4[8192 + i] = w2[i];
    }
    if (tid < 128) { sB[tid] = B0[tid]; sB[128 + tid] = B1[tid]; }
    if (tid < 16)  sB[256 + tid] = 0.f;

    // x tile -> smem (row stride 129 to avoid bank conflicts)
    const int n0 = blockIdx.x * 64;
    for (int i = tid; i < 2048; i += 256) {
        int r = i >> 5, q = i & 31;
        int n = n0 + r;
        float4 v = make_float4(0.f, 0.f, 0.f, 0.f);
        if (n < NN) v = ((const float4*)(A + (size_t)n * 128))[q];
        int b = r * 129 + q * 4;
        sX[b] = v.x; sX[b+1] = v.y; sX[b+2] = v.z; sX[b+3] = v.w;
    }
    __syncthreads();

    const int tx = tid & 15;        // node tile (4 nodes)
    const int ty = tid >> 4;        // out tile base
    const int OT = OUTS / 4;
    for (int ot = ty; ot < OT; ot += 16) {
        float acc[4][4];
        #pragma unroll
        for (int i = 0; i < 4; i++)
            #pragma unroll
            for (int j = 0; j < 4; j++) acc[i][j] = 0.f;

        const float* xb = sX + tx * 4 * 129;
        const float* wb = sW + ot * 4 * 128;
        #pragma unroll 4
        for (int k = 0; k < 128; k++) {
            float x0 = xb[k], x1 = xb[129 + k], x2 = xb[258 + k], x3 = xb[387 + k];
            float wa = wb[k], wbv = wb[128 + k], wc = wb[256 + k], wd = wb[384 + k];
            acc[0][0] = fmaf(x0, wa, acc[0][0]); acc[0][1] = fmaf(x0, wbv, acc[0][1]);
            acc[0][2] = fmaf(x0, wc, acc[0][2]); acc[0][3] = fmaf(x0, wd, acc[0][3]);
            acc[1][0] = fmaf(x1, wa, acc[1][0]); acc[1][1] = fmaf(x1, wbv, acc[1][1]);
            acc[1][2] = fmaf(x1, wc, acc[1][2]); acc[1][3] = fmaf(x1, wd, acc[1][3]);
            acc[2][0] = fmaf(x2, wa, acc[2][0]); acc[2][1] = fmaf(x2, wbv, acc[2][1]);
            acc[2][2] = fmaf(x2, wc, acc[2][2]); acc[2][3] = fmaf(x2, wd, acc[2][3]);
            acc[3][0] = fmaf(x3, wa, acc[3][0]); acc[3][1] = fmaf(x3, wbv, acc[3][1]);
            acc[3][2] = fmaf(x3, wc, acc[3][2]); acc[3][3] = fmaf(x3, wd, acc[3][3]);
        }
        #pragma unroll
        for (int j = 0; j < 4; j++) {
            int o = ot * 4 + j;
            float bv = sB[o];
            #pragma unroll
            for (int i = 0; i < 4; i++) {
                int n = n0 + tx * 4 + i;
                if (n >= NN) continue;
                float v = acc[i][j] + bv;
                if (o < 128)      O0[(size_t)n * 128 + o]       = v;
                else if (o < 256) O1[(size_t)n * 128 + (o-128)] = v;
                else              O2[(size_t)n * 16  + (o-256)] = v;
            }
        }
    }
}

// ---------------- per-node attention aggregation ----------------------------
// block = 128 threads, thread t = (head h = t>>4, channel c = t&15)
__device__ __forceinline__ float head_sum16(float p) {
    p += __shfl_xor_sync(0xffffffffu, p, 8);
    p += __shfl_xor_sync(0xffffffffu, p, 4);
    p += __shfl_xor_sync(0xffffffffu, p, 2);
    p += __shfl_xor_sync(0xffffffffu, p, 1);
    return p;
}

__global__ void __launch_bounds__(128) k_agg1(
    const float* __restrict__ att,  const float* __restrict__ bias,
    const float* __restrict__ bnw,  const float* __restrict__ bnb,
    const float* __restrict__ bnrm, const float* __restrict__ bnrv)
{
    __shared__ int s_src[128];
    const int d = blockIdx.x;
    const int t = threadIdx.x;

    const float xr   = g_xr1[(size_t)d * 128 + t];
    const float attv = att[t];

    // self-loop first (always present) -> initializes online-softmax state
    float xlv = g_xl1[(size_t)d * 128 + t];
    float e = xlv + xr; e = (e > 0.f) ? e : NEG * e;
    float m = head_sum16(e * attv);
    float den = 1.f;
    float acc = xlv;

    const int beg = g_rowptr[d], end = g_rowptr[d + 1];
    for (int base = beg; base < end; base += 128) {
        int nv = min(128, end - base);
        __syncthreads();
        if (t < nv) s_src[t] = g_csr[base + t];
        __syncthreads();
        float xl_n = g_xl1[(size_t)s_src[0] * 128 + t];
        for (int j = 0; j < nv; j++) {
            float x = xl_n;
            if (j + 1 < nv) xl_n = g_xl1[(size_t)s_src[j + 1] * 128 + t];
            float ev = x + xr; ev = (ev > 0.f) ? ev : NEG * ev;
            float s = head_sum16(ev * attv);
            float nm = fmaxf(m, s);
            float sc = __expf(m - nm);
            float w  = __expf(s - nm);
            den = den * sc + w;
            acc = acc * sc + w * x;
            m = nm;
        }
    }
    float val = acc / den + bias[t];
    val = (val - bnrm[t]) * rsqrtf(bnrv[t] + 1e-5f) * bnw[t] + bnb[t];   // BN eval
    val = (val > 0.f) ? val : (__expf(val) - 1.f);                       // ELU
    g_h1[(size_t)d * 128 + t] = val;
}

__global__ void __launch_bounds__(128) k_agg2(
    const float* __restrict__ att, const float* __restrict__ bias2,
    const float* __restrict__ lnw, const float* __restrict__ lnb,
    float* __restrict__ out)
{
    __shared__ int   s_src[128];
    __shared__ float s_acc[128];
    const int d = blockIdx.x;
    const int t = threadIdx.x;

    const float xr   = g_xr2[(size_t)d * 128 + t];
    const float attv = att[t];

    float xlv = g_xl2[(size_t)d * 128 + t];
    float e = xlv + xr; e = (e > 0.f) ? e : NEG * e;
    float m = head_sum16(e * attv);
    float den = 1.f;
    float acc = xlv;

    const int beg = g_rowptr[d], end = g_rowptr[d + 1];
    for (int base = beg; base < end; base += 128) {
        int nv = min(128, end - base);
        __syncthreads();
        if (t < nv) s_src[t] = g_csr[base + t];
        __syncthreads();
        float xl_n = g_xl2[(size_t)s_src[0] * 128 + t];
        for (int j = 0; j < nv; j++) {
            float x = xl_n;
            if (j + 1 < nv) xl_n = g_xl2[(size_t)s_src[j + 1] * 128 + t];
            float ev = x + xr; ev = (ev > 0.f) ? ev : NEG * ev;
            float s = head_sum16(ev * attv);
            float nm = fmaxf(m, s);
            float sc = __expf(m - nm);
            float w  = __expf(s - nm);
            den = den * sc + w;
            acc = acc * sc + w * x;
            m = nm;
        }
    }
    s_acc[t] = acc / den;
    __syncthreads();
    if (t < 16) {
        float v = 0.f;
        #pragma unroll
        for (int h = 0; h < 8; h++) v += s_acc[h * 16 + t];
        v = v * 0.125f + bias2[t] + g_xres[(size_t)d * 16 + t];   // mean heads + bias + skip
        // LayerNorm over 16 channels (lanes 0..15 of warp 0)
        float mu = v;
        mu += __shfl_xor_sync(0xffffu, mu, 8);
        mu += __shfl_xor_sync(0xffffu, mu, 4);
        mu += __shfl_xor_sync(0xffffu, mu, 2);
        mu += __shfl_xor_sync(0xffffu, mu, 1);
        mu *= (1.f / 16.f);
        float dlt = v - mu;
        float var = dlt * dlt;
        var += __shfl_xor_sync(0xffffu, var, 8);
        var += __shfl_xor_sync(0xffffu, var, 4);
        var += __shfl_xor_sync(0xffffu, var, 2);
        var += __shfl_xor_sync(0xffffu, var, 1);
        var *= (1.f / 16.f);
        out[(size_t)d * 16 + t] = dlt * rsqrtf(var + 1e-5f) * lnw[t] + lnb[t];
    }
}

// ---------------- host ------------------------------------------------------
extern "C" void kernel_launch(void* const* d_in, const int* in_sizes, int n_in,
                              void* d_out, int out_size)
{
    const float* x     = (const float*)d_in[0];
    const int*   ei    = (const int*)d_in[1];      // int32: JAX x64 disabled
    const float* Wl1   = (const float*)d_in[2];
    const float* bl1   = (const float*)d_in[3];
    const float* Wr1   = (const float*)d_in[4];
    const float* br1   = (const float*)d_in[5];
    const float* att1  = (const float*)d_in[6];
    const float* bias1 = (const float*)d_in[7];
    const float* bnw   = (const float*)d_in[8];
    const float* bnb   = (const float*)d_in[9];
    const float* bnrm  = (const float*)d_in[10];
    const float* bnrv  = (const float*)d_in[11];
    const float* Wl2   = (const float*)d_in[12];
    const float* bl2   = (const float*)d_in[13];
    const float* Wr2   = (const float*)d_in[14];
    const float* br2   = (const float*)d_in[15];
    const float* att2  = (const float*)d_in[16];
    const float* bias2 = (const float*)d_in[17];
    const float* Wskip = (const float*)d_in[18];
    const float* lnw   = (const float*)d_in[19];
    const float* lnb   = (const float*)d_in[20];
    float*       out   = (float*)d_out;

    float *xl1, *xr1, *h1, *xl2, *xr2, *xres;
    cudaGetSymbolAddress((void**)&xl1,  g_xl1);
    cudaGetSymbolAddress((void**)&xr1,  g_xr1);
    cudaGetSymbolAddress((void**)&h1,   g_h1);
    cudaGetSymbolAddress((void**)&xl2,  g_xl2);
    cudaGetSymbolAddress((void**)&xr2,  g_xr2);
    cudaGetSymbolAddress((void**)&xres, g_xres);

    const int smem1 = (272*128 + 288 + 64*129) * 4;   // 173440 B
    const int smem2 = (256*128 + 288 + 64*129) * 4;   // 165248 B
    cudaFuncSetAttribute(k_gemm<true>,  cudaFuncAttributeMaxDynamicSharedMemorySize, smem1);
    cudaFuncSetAttribute(k_gemm<false>, cudaFuncAttributeMaxDynamicSharedMemorySize, smem2);

    // CSR build (recomputed each call; deterministic)
    k_zero_deg<<<(NN + 255) / 256, 256>>>();
    k_count<<<(EE + 255) / 256, 256>>>(ei);
    k_scan<<<1, 1024>>>();
    k_scatter<<<(EE + 255) / 256, 256>>>(ei);

    // conv1 transforms + skip projection
    k_gemm<true><<<(NN + 63) / 64, 256, smem1>>>(x, Wl1, bl1, Wr1, br1, Wskip,
                                                 xl1, xr1, xres);
    // conv1 aggregation + BN + ELU
    k_agg1<<<NN, 128>>>(att1, bias1, bnw, bnb, bnrm, bnrv);

    // conv2 transforms
    k_gemm<false><<<(NN + 63) / 64, 256, smem2>>>(h1, Wl2, bl2, Wr2, br2, nullptr,
                                                  xl2, xr2, nullptr);
    // conv2 aggregation + head-mean + skip + LayerNorm
    k_agg2<<<NN, 128>>>(att2, bias2, lnw, lnb, out);
}

// round 10
// speedup vs baseline: 1.1063x; 1.1063x over previous
#include <cuda_runtime.h>
#include <cuda_bf16.h>

#define NN   50000
#define EE   800000
#define NEG  0.2f

// ---------------- scratch (static device arrays; no allocation allowed) ----
__device__ float g_xl1 [NN*128];
__device__ float g_xr1 [NN*128];
__device__ float g_h1  [NN*128];
__device__ float g_xl2 [NN*128];
__device__ float g_xr2 [NN*128];
__device__ float g_xres[NN*16];
__device__ int   g_deg [NN];
__device__ int   g_rowptr[NN+1];
__device__ int   g_cursor[NN];
__device__ int   g_csr [EE];

// ---------------- CSR build ------------------------------------------------
__global__ void k_zero_deg() {
    int i = blockIdx.x*256 + threadIdx.x;
    if (i < NN) g_deg[i] = 0;
}

// edge_index is int32 (JAX x64 disabled): row 0 = src [0..E), row 1 = dst [E..2E)
__global__ void k_count(const int* __restrict__ ei) {
    int e = blockIdx.x*256 + threadIdx.x;
    if (e < EE) {
        unsigned dst = (unsigned)ei[EE + e];
        if (dst < NN) atomicAdd(&g_deg[dst], 1);
    }
}

__global__ void __launch_bounds__(1024) k_scan() {
    __shared__ int s[1024];
    const int tid = threadIdx.x;
    const int per = (NN + 1023) / 1024;          // 49
    int start = tid * per;
    int stop  = min(start + per, NN);
    int sum = 0;
    for (int i = start; i < stop; i++) sum += g_deg[i];
    s[tid] = sum;
    __syncthreads();
    for (int off = 1; off < 1024; off <<= 1) {
        int v = (tid >= off) ? s[tid - off] : 0;
        __syncthreads();
        s[tid] += v;
        __syncthreads();
    }
    int run = s[tid] - sum;                      // exclusive offset for this chunk
    for (int i = start; i < stop; i++) {
        g_rowptr[i] = run;
        g_cursor[i] = run;
        run += g_deg[i];
    }
    // total kept edges = last thread's post-loop running value (inclusive total)
    if (tid == 1023) g_rowptr[NN] = run;
}

__global__ void k_scatter(const int* __restrict__ ei) {
    int e = blockIdx.x*256 + threadIdx.x;
    if (e < EE) {
        unsigned src = (unsigned)ei[e];
        unsigned dst = (unsigned)ei[EE + e];
        if (dst < NN && src < NN) {
            int pos = atomicAdd(&g_cursor[dst], 1);
            g_csr[pos] = (int)src;
        }
    }
}

// ---------------- fused SIMT GEMM (exact fp32, float4 inner loop) ----------
__device__ __forceinline__ void dot4(const float4 a, const float4 b, float& d) {
    d = fmaf(a.x, b.x, d);
    d = fmaf(a.y, b.y, d);
    d = fmaf(a.z, b.z, d);
    d = fmaf(a.w, b.w, d);
}

// out[n][o] = sum_k A[n][k] * Wcat[o][k] + bias[o]
// x tile: sX[node][k], row stride 132 floats (16B aligned, conflict-free with
// strided node->lane mapping). W tile: sW[o][k], row stride 128 (broadcast).
#define XSTR 132
template<bool SKIP>
__global__ void __launch_bounds__(256) k_gemm(
    const float* __restrict__ A,
    const float* __restrict__ W0, const float* __restrict__ B0,
    const float* __restrict__ W1, const float* __restrict__ B1,
    const float* __restrict__ W2,
    float* __restrict__ O0, float* __restrict__ O1, float* __restrict__ O2)
{
    const int OUTS = SKIP ? 272 : 256;
    extern __shared__ float sm[];
    float* sW = sm;                 // OUTS*128
    float* sB = sW + OUTS*128;      // 288 (padded)
    float* sX = sB + 288;           // 64*XSTR

    const int tid = threadIdx.x;

    // weights -> smem (contiguous, float4)
    float4* sw4 = (float4*)sW;
    const float4* w0g = (const float4*)W0;
    for (int i = tid; i < 4096; i += 256) sw4[i] = w0g[i];
    const float4* w1g = (const float4*)W1;
    for (int i = tid; i < 4096; i += 256) sw4[4096 + i] = w1g[i];
    if (SKIP) {
        const float4* w2g = (const float4*)W2;
        for (int i = tid; i < 512; i += 256) sw4[8192 + i] = w2g[i];
    }
    if (tid < 128) { sB[tid] = B0[tid]; sB[128 + tid] = B1[tid]; }
    if (tid < 16)  sB[256 + tid] = 0.f;

    // x tile -> smem (row stride XSTR floats)
    const int n0 = blockIdx.x * 64;
    for (int i = tid; i < 2048; i += 256) {
        int r = i >> 5, q = i & 31;         // consecutive tid -> consecutive q (coalesced)
        int n = n0 + r;
        float4 v = make_float4(0.f, 0.f, 0.f, 0.f);
        if (n < NN) v = ((const float4*)(A + (size_t)n * 128))[q];
        ((float4*)(sX + r * XSTR))[q] = v;
    }
    __syncthreads();

    const int tx = tid & 15;        // node lane: nodes tx, tx+16, tx+32, tx+48
    const int ty = tid >> 4;        // out tile base
    const int OT = OUTS / 4;

    const float4* x0 = (const float4*)(sX + (tx     ) * XSTR);
    const float4* x1 = (const float4*)(sX + (tx + 16) * XSTR);
    const float4* x2 = (const float4*)(sX + (tx + 32) * XSTR);
    const float4* x3 = (const float4*)(sX + (tx + 48) * XSTR);

    for (int ot = ty; ot < OT; ot += 16) {
        float acc[4][4];
        #pragma unroll
        for (int i = 0; i < 4; i++)
            #pragma unroll
            for (int j = 0; j < 4; j++) acc[i][j] = 0.f;

        const float4* w0p = (const float4*)(sW + (ot * 4 + 0) * 128);
        const float4* w1p = (const float4*)(sW + (ot * 4 + 1) * 128);
        const float4* w2p = (const float4*)(sW + (ot * 4 + 2) * 128);
        const float4* w3p = (const float4*)(sW + (ot * 4 + 3) * 128);

        #pragma unroll 4
        for (int kq = 0; kq < 32; kq++) {
            float4 xa = x0[kq], xb = x1[kq], xc = x2[kq], xd = x3[kq];
            float4 wa = w0p[kq], wb = w1p[kq], wc = w2p[kq], wd = w3p[kq];
            dot4(xa, wa, acc[0][0]); dot4(xa, wb, acc[0][1]); dot4(xa, wc, acc[0][2]); dot4(xa, wd, acc[0][3]);
            dot4(xb, wa, acc[1][0]); dot4(xb, wb, acc[1][1]); dot4(xb, wc, acc[1][2]); dot4(xb, wd, acc[1][3]);
            dot4(xc, wa, acc[2][0]); dot4(xc, wb, acc[2][1]); dot4(xc, wc, acc[2][2]); dot4(xc, wd, acc[2][3]);
            dot4(xd, wa, acc[3][0]); dot4(xd, wb, acc[3][1]); dot4(xd, wc, acc[3][2]); dot4(xd, wd, acc[3][3]);
        }
        #pragma unroll
        for (int j = 0; j < 4; j++) {
            int o = ot * 4 + j;
            float bv = sB[o];
            #pragma unroll
            for (int i = 0; i < 4; i++) {
                int n = n0 + tx + 16 * i;
                if (n >= NN) continue;
                float v = acc[i][j] + bv;
                if (o < 128)      O0[(size_t)n * 128 + o]       = v;
                else if (o < 256) O1[(size_t)n * 128 + (o-128)] = v;
                else              O2[(size_t)n * 16  + (o-256)] = v;
            }
        }
    }
}

// ---------------- per-node attention aggregation ----------------------------
// block = 128 threads, thread t = (head h = t>>4, channel c = t&15)
// Softmax uses the self-loop score as a fixed baseline (shift-invariant; scores
// are bounded to a few units here) -> no serial online-softmax chain per edge.
__device__ __forceinline__ float head_sum16(float p) {
    p += __shfl_xor_sync(0xffffffffu, p, 8);
    p += __shfl_xor_sync(0xffffffffu, p, 4);
    p += __shfl_xor_sync(0xffffffffu, p, 2);
    p += __shfl_xor_sync(0xffffffffu, p, 1);
    return p;
}

template<int LAYER>
__device__ __forceinline__ void agg_body(
    const float* __restrict__ xlbuf, float xr, float attv, float xlv,
    int beg, int end, int t, float& den_out, float& acc_out)
{
    __shared__ int s_src[128];
    float e = xlv + xr; e = (e > 0.f) ? e : NEG * e;
    const float m0 = head_sum16(e * attv);    // self-loop score = baseline
    float den = 1.f;                           // exp(m0 - m0)
    float acc = xlv;

    for (int base = beg; base < end; base += 128) {
        int nv = min(128, end - base);
        __syncthreads();
        if (t < nv) s_src[t] = g_csr[base + t];
        __syncthreads();
        int j = 0;
        for (; j + 2 <= nv; j += 2) {
            float xa = xlbuf[(size_t)s_src[j]     * 128 + t];
            float xb = xlbuf[(size_t)s_src[j + 1] * 128 + t];
            float ea = xa + xr; ea = (ea > 0.f) ? ea : NEG * ea;
            float eb = xb + xr; eb = (eb > 0.f) ? eb : NEG * eb;
            float sa = head_sum16(ea * attv);
            float sb = head_sum16(eb * attv);
            float wa = __expf(sa - m0);
            float wb = __expf(sb - m0);
            den += wa + wb;
            acc = fmaf(wa, xa, fmaf(wb, xb, acc));
        }
        if (j < nv) {
            float xa = xlbuf[(size_t)s_src[j] * 128 + t];
            float ea = xa + xr; ea = (ea > 0.f) ? ea : NEG * ea;
            float sa = head_sum16(ea * attv);
            float wa = __expf(sa - m0);
            den += wa;
            acc = fmaf(wa, xa, acc);
        }
    }
    den_out = den; acc_out = acc;
}

__global__ void __launch_bounds__(128) k_agg1(
    const float* __restrict__ att,  const float* __restrict__ bias,
    const float* __restrict__ bnw,  const float* __restrict__ bnb,
    const float* __restrict__ bnrm, const float* __restrict__ bnrv)
{
    const int d = blockIdx.x;
    const int t = threadIdx.x;

    const float xr   = g_xr1[(size_t)d * 128 + t];
    const float attv = att[t];
    const float xlv  = g_xl1[(size_t)d * 128 + t];

    float den, acc;
    agg_body<1>(g_xl1, xr, attv, xlv, g_rowptr[d], g_rowptr[d + 1], t, den, acc);

    float val = acc / den + bias[t];
    val = (val - bnrm[t]) * rsqrtf(bnrv[t] + 1e-5f) * bnw[t] + bnb[t];   // BN eval
    val = (val > 0.f) ? val : (__expf(val) - 1.f);                       // ELU
    g_h1[(size_t)d * 128 + t] = val;
}

__global__ void __launch_bounds__(128) k_agg2(
    const float* __restrict__ att, const float* __restrict__ bias2,
    const float* __restrict__ lnw, const float* __restrict__ lnb,
    float* __restrict__ out)
{
    __shared__ float s_acc[128];
    const int d = blockIdx.x;
    const int t = threadIdx.x;

    const float xr   = g_xr2[(size_t)d * 128 + t];
    const float attv = att[t];
    const float xlv  = g_xl2[(size_t)d * 128 + t];

    float den, acc;
    agg_body<2>(g_xl2, xr, attv, xlv, g_rowptr[d], g_rowptr[d + 1], t, den, acc);

    s_acc[t] = acc / den;
    __syncthreads();
    if (t < 16) {
        float v = 0.f;
        #pragma unroll
        for (int h = 0; h < 8; h++) v += s_acc[h * 16 + t];
        v = v * 0.125f + bias2[t] + g_xres[(size_t)d * 16 + t];   // mean heads + bias + skip
        // LayerNorm over 16 channels (lanes 0..15 of warp 0)
        float mu = v;
        mu += __shfl_xor_sync(0xffffu, mu, 8);
        mu += __shfl_xor_sync(0xffffu, mu, 4);
        mu += __shfl_xor_sync(0xffffu, mu, 2);
        mu += __shfl_xor_sync(0xffffu, mu, 1);
        mu *= (1.f / 16.f);
        float dlt = v - mu;
        float var = dlt * dlt;
        var += __shfl_xor_sync(0xffffu, var, 8);
        var += __shfl_xor_sync(0xffffu, var, 4);
        var += __shfl_xor_sync(0xffffu, var, 2);
        var += __shfl_xor_sync(0xffffu, var, 1);
        var *= (1.f / 16.f);
        out[(size_t)d * 16 + t] = dlt * rsqrtf(var + 1e-5f) * lnw[t] + lnb[t];
    }
}

// ---------------- host ------------------------------------------------------
extern "C" void kernel_launch(void* const* d_in, const int* in_sizes, int n_in,
                              void* d_out, int out_size)
{
    const float* x     = (const float*)d_in[0];
    const int*   ei    = (const int*)d_in[1];      // int32: JAX x64 disabled
    const float* Wl1   = (const float*)d_in[2];
    const float* bl1   = (const float*)d_in[3];
    const float* Wr1   = (const float*)d_in[4];
    const float* br1   = (const float*)d_in[5];
    const float* att1  = (const float*)d_in[6];
    const float* bias1 = (const float*)d_in[7];
    const float* bnw   = (const float*)d_in[8];
    const float* bnb   = (const float*)d_in[9];
    const float* bnrm  = (const float*)d_in[10];
    const float* bnrv  = (const float*)d_in[11];
    const float* Wl2   = (const float*)d_in[12];
    const float* bl2   = (const float*)d_in[13];
    const float* Wr2   = (const float*)d_in[14];
    const float* br2   = (const float*)d_in[15];
    const float* att2  = (const float*)d_in[16];
    const float* bias2 = (const float*)d_in[17];
    const float* Wskip = (const float*)d_in[18];
    const float* lnw   = (const float*)d_in[19];
    const float* lnb   = (const float*)d_in[20];
    float*       out   = (float*)d_out;

    float *xl1, *xr1, *h1, *xl2, *xr2, *xres;
    cudaGetSymbolAddress((void**)&xl1,  g_xl1);
    cudaGetSymbolAddress((void**)&xr1,  g_xr1);
    cudaGetSymbolAddress((void**)&h1,   g_h1);
    cudaGetSymbolAddress((void**)&xl2,  g_xl2);
    cudaGetSymbolAddress((void**)&xr2,  g_xr2);
    cudaGetSymbolAddress((void**)&xres, g_xres);

    const int smem1 = (272*128 + 288 + 64*XSTR) * 4;
    const int smem2 = (256*128 + 288 + 64*XSTR) * 4;
    cudaFuncSetAttribute(k_gemm<true>,  cudaFuncAttributeMaxDynamicSharedMemorySize, smem1);
    cudaFuncSetAttribute(k_gemm<false>, cudaFuncAttributeMaxDynamicSharedMemorySize, smem2);

    // CSR build (recomputed each call; deterministic)
    k_zero_deg<<<(NN + 255) / 256, 256>>>();
    k_count<<<(EE + 255) / 256, 256>>>(ei);
    k_scan<<<1, 1024>>>();
    k_scatter<<<(EE + 255) / 256, 256>>>(ei);

    // conv1 transforms + skip projection
    k_gemm<true><<<(NN + 63) / 64, 256, smem1>>>(x, Wl1, bl1, Wr1, br1, Wskip,
                                                 xl1, xr1, xres);
    // conv1 aggregation + BN + ELU
    k_agg1<<<NN, 128>>>(att1, bias1, bnw, bnb, bnrm, bnrv);

    // conv2 transforms
    k_gemm<false><<<(NN + 63) / 64, 256, smem2>>>(h1, Wl2, bl2, Wr2, br2, nullptr,
                                                  xl2, xr2, nullptr);
    // conv2 aggregation + head-mean + skip + LayerNorm
    k_agg2<<<NN, 128>>>(att2, bias2, lnw, lnb, out);
}

// round 11
// speedup vs baseline: 1.4470x; 1.3079x over previous
#include <cuda_runtime.h>
#include <cuda_bf16.h>

#define NN   50000
#define EE   800000
#define NEG  0.2f

// ---------------- scratch (static device arrays; no allocation allowed) ----
__device__ float g_xl1 [NN*128];
__device__ float g_xr1 [NN*128];
__device__ float g_h1  [NN*128];
__device__ float g_xl2 [NN*128];
__device__ float g_xr2 [NN*128];
__device__ float g_xres[NN*16];
__device__ int   g_deg [NN];
__device__ int   g_rowptr[NN+1];
__device__ int   g_cursor[NN];
__device__ int   g_csr [EE];

// ---------------- CSR build ------------------------------------------------
__global__ void k_zero_deg() {
    int i = blockIdx.x*256 + threadIdx.x;
    if (i < NN) g_deg[i] = 0;
}

// edge_index is int32 (JAX x64 disabled): row 0 = src [0..E), row 1 = dst [E..2E)
__global__ void k_count(const int* __restrict__ ei) {
    int e = blockIdx.x*256 + threadIdx.x;
    if (e < EE) {
        unsigned dst = (unsigned)ei[EE + e];
        if (dst < NN) atomicAdd(&g_deg[dst], 1);
    }
}

__global__ void __launch_bounds__(1024) k_scan() {
    __shared__ int s[1024];
    const int tid = threadIdx.x;
    const int per = (NN + 1023) / 1024;          // 49
    int start = tid * per;
    int stop  = min(start + per, NN);
    int sum = 0;
    for (int i = start; i < stop; i++) sum += g_deg[i];
    s[tid] = sum;
    __syncthreads();
    for (int off = 1; off < 1024; off <<= 1) {
        int v = (tid >= off) ? s[tid - off] : 0;
        __syncthreads();
        s[tid] += v;
        __syncthreads();
    }
    int run = s[tid] - sum;                      // exclusive offset for this chunk
    for (int i = start; i < stop; i++) {
        g_rowptr[i] = run;
        g_cursor[i] = run;
        run += g_deg[i];
    }
    // total kept edges = last thread's post-loop running value (inclusive total)
    if (tid == 1023) g_rowptr[NN] = run;
}

__global__ void k_scatter(const int* __restrict__ ei) {
    int e = blockIdx.x*256 + threadIdx.x;
    if (e < EE) {
        unsigned src = (unsigned)ei[e];
        unsigned dst = (unsigned)ei[EE + e];
        if (dst < NN && src < NN) {
            int pos = atomicAdd(&g_cursor[dst], 1);
            g_csr[pos] = (int)src;
        }
    }
}

// ---------------- SIMT GEMM: 128 nodes x 64 outs per block ------------------
// gridDim.x = node tiles, gridDim.y = out chunks of 64 over concat [W0;W1;W2].
// smem ~102KB -> 2 blocks/SM (16 warps). Thread tile 8 nodes x 4 outs.
__device__ __forceinline__ void dot4(const float4 a, const float4 b, float& d) {
    d = fmaf(a.x, b.x, d);
    d = fmaf(a.y, b.y, d);
    d = fmaf(a.z, b.z, d);
    d = fmaf(a.w, b.w, d);
}

#define XSTR 132
#define WSTR 132

__global__ void __launch_bounds__(256) k_gemm(
    const float* __restrict__ A,
    const float* __restrict__ W0, const float* __restrict__ B0,
    const float* __restrict__ W1, const float* __restrict__ B1,
    const float* __restrict__ W2,
    float* __restrict__ O0, float* __restrict__ O1, float* __restrict__ O2,
    int outs_total)
{
    extern __shared__ float sm[];
    float* sW = sm;                    // 64*WSTR
    float* sX = sW + 64*WSTR;          // 128*XSTR
    float* sB = sX + 128*XSTR;         // 64

    const int tid = threadIdx.x;
    const int ob  = blockIdx.y * 64;
    const int rows = min(64, outs_total - ob);   // 64 or 16 (skip chunk)

    const float* Wsrc; const float* Bsrc;
    if (ob < 128)      { Wsrc = W0 + ob*128;           Bsrc = B0 + ob; }
    else if (ob < 256) { Wsrc = W1 + (ob-128)*128;     Bsrc = B1 + (ob-128); }
    else               { Wsrc = W2;                    Bsrc = nullptr; }

    // W chunk -> smem (row stride WSTR floats)
    const float4* wg = (const float4*)Wsrc;
    for (int i = tid; i < rows*32; i += 256) {
        int r = i >> 5, q = i & 31;
        ((float4*)(sW + r*WSTR))[q] = wg[r*32 + q];
    }
    if (tid < 64) sB[tid] = (tid < rows && Bsrc) ? Bsrc[tid] : 0.f;

    // X tile (128 nodes) -> smem
    const int n0 = blockIdx.x * 128;
    for (int i = tid; i < 4096; i += 256) {
        int r = i >> 5, q = i & 31;
        int n = n0 + r;
        float4 v = make_float4(0.f, 0.f, 0.f, 0.f);
        if (n < NN) v = ((const float4*)(A + (size_t)n * 128))[q];
        ((float4*)(sX + r*XSTR))[q] = v;
    }
    __syncthreads();

    const int tx = tid & 15;          // node lane: nodes tx + 16*i, i=0..7
    const int ty = tid >> 4;          // out group: outs ty*4 .. ty*4+3

    if (ty * 4 < rows) {
        float acc[8][4];
        #pragma unroll
        for (int i = 0; i < 8; i++)
            #pragma unroll
            for (int j = 0; j < 4; j++) acc[i][j] = 0.f;

        const float4* wp0 = (const float4*)(sW + (ty*4 + 0) * WSTR);
        const float4* wp1 = (const float4*)(sW + (ty*4 + 1) * WSTR);
        const float4* wp2 = (const float4*)(sW + (ty*4 + 2) * WSTR);
        const float4* wp3 = (const float4*)(sW + (ty*4 + 3) * WSTR);

        #pragma unroll 2
        for (int kq = 0; kq < 32; kq++) {
            float4 wv0 = wp0[kq], wv1 = wp1[kq], wv2 = wp2[kq], wv3 = wp3[kq];
            #pragma unroll
            for (int i = 0; i < 8; i++) {
                float4 xv = ((const float4*)(sX + (tx + 16*i) * XSTR))[kq];
                dot4(xv, wv0, acc[i][0]);
                dot4(xv, wv1, acc[i][1]);
                dot4(xv, wv2, acc[i][2]);
                dot4(xv, wv3, acc[i][3]);
            }
        }

        #pragma unroll
        for (int j = 0; j < 4; j++) {
            int o = ob + ty*4 + j;
            float bv = sB[ty*4 + j];
            #pragma unroll
            for (int i = 0; i < 8; i++) {
                int n = n0 + tx + 16*i;
                if (n >= NN) continue;
                float v = acc[i][j] + bv;
                if (o < 128)      O0[(size_t)n * 128 + o]       = v;
                else if (o < 256) O1[(size_t)n * 128 + (o-128)] = v;
                else              O2[(size_t)n * 16  + (o-256)] = v;
            }
        }
    }
}

// ---------------- per-node attention aggregation ----------------------------
// block = 128 threads, thread t = (head h = t>>4, channel c = t&15)
// Softmax uses the self-loop score as a fixed baseline (shift-invariant; scores
// are bounded to a few units here) -> edges fully independent, unroll 4.
__device__ __forceinline__ float head_sum16(float p) {
    p += __shfl_xor_sync(0xffffffffu, p, 8);
    p += __shfl_xor_sync(0xffffffffu, p, 4);
    p += __shfl_xor_sync(0xffffffffu, p, 2);
    p += __shfl_xor_sync(0xffffffffu, p, 1);
    return p;
}

__device__ __forceinline__ void agg_body(
    const float* __restrict__ xlbuf, float xr, float attv, float xlv,
    int beg, int end, int t, float& den_out, float& acc_out)
{
    __shared__ int s_src[128];
    float e = xlv + xr; e = (e > 0.f) ? e : NEG * e;
    const float m0 = head_sum16(e * attv);    // self-loop score = baseline
    float den = 1.f;                           // exp(m0 - m0)
    float acc = xlv;

    for (int base = beg; base < end; base += 128) {
        int nv = min(128, end - base);
        __syncthreads();
        if (t < nv) s_src[t] = g_csr[base + t];
        __syncthreads();
        int j = 0;
        for (; j + 4 <= nv; j += 4) {
            float xa = xlbuf[(size_t)s_src[j]     * 128 + t];
            float xb = xlbuf[(size_t)s_src[j + 1] * 128 + t];
            float xc = xlbuf[(size_t)s_src[j + 2] * 128 + t];
            float xd = xlbuf[(size_t)s_src[j + 3] * 128 + t];
            float ea = xa + xr; ea = (ea > 0.f) ? ea : NEG * ea;
            float eb = xb + xr; eb = (eb > 0.f) ? eb : NEG * eb;
            float ec = xc + xr; ec = (ec > 0.f) ? ec : NEG * ec;
            float ed = xd + xr; ed = (ed > 0.f) ? ed : NEG * ed;
            float sa = head_sum16(ea * attv);
            float sb = head_sum16(eb * attv);
            float sc = head_sum16(ec * attv);
            float sd = head_sum16(ed * attv);
            float wa = __expf(sa - m0);
            float wb = __expf(sb - m0);
            float wc = __expf(sc - m0);
            float wd = __expf(sd - m0);
            den += (wa + wb) + (wc + wd);
            acc = fmaf(wa, xa, fmaf(wb, xb, fmaf(wc, xc, fmaf(wd, xd, acc))));
        }
        for (; j < nv; j++) {
            float xa = xlbuf[(size_t)s_src[j] * 128 + t];
            float ea = xa + xr; ea = (ea > 0.f) ? ea : NEG * ea;
            float sa = head_sum16(ea * attv);
            float wa = __expf(sa - m0);
            den += wa;
            acc = fmaf(wa, xa, acc);
        }
    }
    den_out = den; acc_out = acc;
}

__global__ void __launch_bounds__(128) k_agg1(
    const float* __restrict__ att,  const float* __restrict__ bias,
    const float* __restrict__ bnw,  const float* __restrict__ bnb,
    const float* __restrict__ bnrm, const float* __restrict__ bnrv)
{
    const int d = blockIdx.x;
    const int t = threadIdx.x;

    const float xr   = g_xr1[(size_t)d * 128 + t];
    const float attv = att[t];
    const float xlv  = g_xl1[(size_t)d * 128 + t];

    float den, acc;
    agg_body(g_xl1, xr, attv, xlv, g_rowptr[d], g_rowptr[d + 1], t, den, acc);

    float val = acc / den + bias[t];
    val = (val - bnrm[t]) * rsqrtf(bnrv[t] + 1e-5f) * bnw[t] + bnb[t];   // BN eval
    val = (val > 0.f) ? val : (__expf(val) - 1.f);                       // ELU
    g_h1[(size_t)d * 128 + t] = val;
}

__global__ void __launch_bounds__(128) k_agg2(
    const float* __restrict__ att, const float* __restrict__ bias2,
    const float* __restrict__ lnw, const float* __restrict__ lnb,
    float* __restrict__ out)
{
    __shared__ float s_acc[128];
    const int d = blockIdx.x;
    const int t = threadIdx.x;

    const float xr   = g_xr2[(size_t)d * 128 + t];
    const float attv = att[t];
    const float xlv  = g_xl2[(size_t)d * 128 + t];

    float den, acc;
    agg_body(g_xl2, xr, attv, xlv, g_rowptr[d], g_rowptr[d + 1], t, den, acc);

    s_acc[t] = acc / den;
    __syncthreads();
    if (t < 16) {
        float v = 0.f;
        #pragma unroll
        for (int h = 0; h < 8; h++) v += s_acc[h * 16 + t];
        v = v * 0.125f + bias2[t] + g_xres[(size_t)d * 16 + t];   // mean heads + bias + skip
        // LayerNorm over 16 channels (lanes 0..15 of warp 0)
        float mu = v;
        mu += __shfl_xor_sync(0xffffu, mu, 8);
        mu += __shfl_xor_sync(0xffffu, mu, 4);
        mu += __shfl_xor_sync(0xffffu, mu, 2);
        mu += __shfl_xor_sync(0xffffu, mu, 1);
        mu *= (1.f / 16.f);
        float dlt = v - mu;
        float var = dlt * dlt;
        var += __shfl_xor_sync(0xffffu, var, 8);
        var += __shfl_xor_sync(0xffffu, var, 4);
        var += __shfl_xor_sync(0xffffu, var, 2);
        var += __shfl_xor_sync(0xffffu, var, 1);
        var *= (1.f / 16.f);
        out[(size_t)d * 16 + t] = dlt * rsqrtf(var + 1e-5f) * lnw[t] + lnb[t];
    }
}

// ---------------- host ------------------------------------------------------
extern "C" void kernel_launch(void* const* d_in, const int* in_sizes, int n_in,
                              void* d_out, int out_size)
{
    const float* x     = (const float*)d_in[0];
    const int*   ei    = (const int*)d_in[1];      // int32: JAX x64 disabled
    const float* Wl1   = (const float*)d_in[2];
    const float* bl1   = (const float*)d_in[3];
    const float* Wr1   = (const float*)d_in[4];
    const float* br1   = (const float*)d_in[5];
    const float* att1  = (const float*)d_in[6];
    const float* bias1 = (const float*)d_in[7];
    const float* bnw   = (const float*)d_in[8];
    const float* bnb   = (const float*)d_in[9];
    const float* bnrm  = (const float*)d_in[10];
    const float* bnrv  = (const float*)d_in[11];
    const float* Wl2   = (const float*)d_in[12];
    const float* bl2   = (const float*)d_in[13];
    const float* Wr2   = (const float*)d_in[14];
    const float* br2   = (const float*)d_in[15];
    const float* att2  = (const float*)d_in[16];
    const float* bias2 = (const float*)d_in[17];
    const float* Wskip = (const float*)d_in[18];
    const float* lnw   = (const float*)d_in[19];
    const float* lnb   = (const float*)d_in[20];
    float*       out   = (float*)d_out;

    float *xl1, *xr1, *h1, *xl2, *xr2, *xres;
    cudaGetSymbolAddress((void**)&xl1,  g_xl1);
    cudaGetSymbolAddress((void**)&xr1,  g_xr1);
    cudaGetSymbolAddress((void**)&h1,   g_h1);
    cudaGetSymbolAddress((void**)&xl2,  g_xl2);
    cudaGetSymbolAddress((void**)&xr2,  g_xr2);
    cudaGetSymbolAddress((void**)&xres, g_xres);

    const int smem = (64*WSTR + 128*XSTR + 64) * 4;   // ~101.6 KB
    cudaFuncSetAttribute(k_gemm, cudaFuncAttributeMaxDynamicSharedMemorySize, smem);

    // CSR build (recomputed each call; deterministic)
    k_zero_deg<<<(NN + 255) / 256, 256>>>();
    k_count<<<(EE + 255) / 256, 256>>>(ei);
    k_scan<<<1, 1024>>>();
    k_scatter<<<(EE + 255) / 256, 256>>>(ei);

    const int NTILES = (NN + 127) / 128;   // 391

    // conv1 transforms + skip projection (outs = 128+128+16 = 272 -> 5 chunks)
    k_gemm<<<dim3(NTILES, 5), 256, smem>>>(x, Wl1, bl1, Wr1, br1, Wskip,
                                           xl1, xr1, xres, 272);
    // conv1 aggregation + BN + ELU
    k_agg1<<<NN, 128>>>(att1, bias1, bnw, bnb, bnrm, bnrv);

    // conv2 transforms (outs = 256 -> 4 chunks)
    k_gemm<<<dim3(NTILES, 4), 256, smem>>>(h1, Wl2, bl2, Wr2, br2, nullptr,
                                           xl2, xr2, nullptr, 256);
    // conv2 aggregation + head-mean + skip + LayerNorm
    k_agg2<<<NN, 128>>>(att2, bias2, lnw, lnb, out);
}